// round 14
// baseline (speedup 1.0000x reference)
#include <cuda_runtime.h>
#include <cuda_fp16.h>

#define IN_DIM   8192
#define OUT_DIM  16384
#define B_ROWS   2048

constexpr int THREADS      = 512;
constexpr int SLAB_ROWS    = 4;                    // fp16 rows per 8B smem slot
constexpr int ROWS_PER_CTA = SLAB_ROWS;
constexpr int COLS_PER_THR = OUT_DIM / THREADS;    // 32 (1 col per iter)
constexpr int SMEM_BYTES   = IN_DIM * SLAB_ROWS * 2;  // 64 KB -> 3 CTAs/SM

// 8-byte slot holding 4 fp16 batch rows of one input column.
struct alignas(8) H4 { half2 h[2]; };
// 8-byte fp16 coefficient quad: {c1, ca}, {cb, cab}.
struct alignas(8) CF4 { __half2 p01; __half2 p23; };

// Precomputed per-output-column data.
__device__ CF4      g_cf [OUT_DIM];   // out = c1 + ca*a + cb*b + cab*ab
__device__ unsigned g_idx[OUT_DIM];   // idx_a | (idx_b << 16)

// ---------------------------------------------------------------------------
// Kernel 1: softmax(weights) -> affine coefficients (fp16); pack idx pairs.
// ---------------------------------------------------------------------------
__global__ void coef_kernel(const float* __restrict__ w,
                            const int*   __restrict__ idx_a,
                            const int*   __restrict__ idx_b)
{
    int o = blockIdx.x * blockDim.x + threadIdx.x;
    if (o >= OUT_DIM) return;

    const float4* w4 = reinterpret_cast<const float4*>(w + (size_t)o * 16);
    float v[16];
#pragma unroll
    for (int q = 0; q < 4; q++) {
        float4 t = w4[q];
        v[4 * q + 0] = t.x; v[4 * q + 1] = t.y;
        v[4 * q + 2] = t.z; v[4 * q + 3] = t.w;
    }

    float m = -1e30f;
#pragma unroll
    for (int i = 0; i < 16; i++) m = fmaxf(m, v[i]);
    float s = 0.0f;
#pragma unroll
    for (int i = 0; i < 16; i++) {
        v[i] = __expf(v[i] - m);
        s += v[i];
    }
    float inv = 1.0f / s;
#pragma unroll
    for (int i = 0; i < 16; i++) v[i] *= inv;

    // Gate table (difflogic order); gate 0 == 0 so v[0] unused.
    float c1  = v[8] + v[9] + v[10] + v[11] + v[12] + v[13] + v[14] + v[15];
    float ca  = v[2] + v[3] + v[6] + v[7] - v[8] - v[9] - v[12] - v[13];
    float cb  = v[4] + v[5] + v[6] + v[7] - v[8] - v[9] - v[10] - v[11];
    float cab = v[1] - v[2] - v[4] - 2.0f * v[6] - v[7]
              + v[8] + 2.0f * v[9] + v[11] + v[13] - v[14];

    CF4 cf;
    cf.p01 = __floats2half2_rn(c1, ca);
    cf.p23 = __floats2half2_rn(cb, cab);
    g_cf[o]  = cf;
    g_idx[o] = (unsigned)idx_a[o] | ((unsigned)idx_b[o] << 16);
}

// ---------------------------------------------------------------------------
// Kernel 2: slim CTA = 4 batch rows x all 16384 cols; 64 KB smem + <=42 regs
// -> 3 CTAs/SM = 48 warps/SM to fill latency gaps.
// ---------------------------------------------------------------------------
__global__ __launch_bounds__(THREADS, 3)
void logic_kernel(const float* __restrict__ x,
                  float*       __restrict__ out)
{
    extern __shared__ H4 sx[];  // sx[col].h[p] = rows {2p, 2p+1} of column col

    const int row0 = blockIdx.x * ROWS_PER_CTA;
    const int lane = threadIdx.x & 31;
    const int warp = threadIdx.x >> 5;
    constexpr int NWARPS = THREADS / 32;

    // Transposed fp16 staging: per 32-column group, 4 coalesced row loads,
    // convert to half, one contiguous STS.64 per lane (conflict-free).
    const float* xb = x + (size_t)row0 * IN_DIM;
#pragma unroll
    for (int g = warp; g < IN_DIM / 32; g += NWARPS) {
        int col = g * 32 + lane;
        H4 v;
        v.h[0] = make_half2(__float2half_rn(xb[(size_t)0 * IN_DIM + col]),
                            __float2half_rn(xb[(size_t)1 * IN_DIM + col]));
        v.h[1] = make_half2(__float2half_rn(xb[(size_t)2 * IN_DIM + col]),
                            __float2half_rn(xb[(size_t)3 * IN_DIM + col]));
        sx[col] = v;
    }
    __syncthreads();

#pragma unroll 4
    for (int c = 0; c < COLS_PER_THR; c++) {
        const int col = c * THREADS + threadIdx.x;

        const unsigned id = g_idx[col];
        const CF4      cw = g_cf[col];

        const H4 a4 = sx[id & 0xFFFFu];   // 4 batch rows in one LDS.64
        const H4 b4 = sx[id >> 16];

        const float2 c01 = __half22float2(cw.p01);  // {c1, ca}
        const float2 c23 = __half22float2(cw.p23);  // {cb, cab}

        float* o0 = out + (size_t)row0 * OUT_DIM + col;
#pragma unroll
        for (int p = 0; p < 2; p++) {
            float2 af = __half22float2(a4.h[p]);
            float2 bf = __half22float2(b4.h[p]);
            __stcs(o0 + (size_t)(2 * p + 0) * OUT_DIM,
                   fmaf(c23.y, af.x * bf.x, fmaf(c23.x, bf.x, fmaf(c01.y, af.x, c01.x))));
            __stcs(o0 + (size_t)(2 * p + 1) * OUT_DIM,
                   fmaf(c23.y, af.y * bf.y, fmaf(c23.x, bf.y, fmaf(c01.y, af.y, c01.x))));
        }
    }
}

// ---------------------------------------------------------------------------
// Launch
// ---------------------------------------------------------------------------
extern "C" void kernel_launch(void* const* d_in, const int* in_sizes, int n_in,
                              void* d_out, int out_size)
{
    const float* x  = (const float*)d_in[0];   // [2048, 8192] f32
    const float* w  = (const float*)d_in[1];   // [16384, 16]  f32
    const int*   ia = (const int*)d_in[2];     // [16384] i32
    const int*   ib = (const int*)d_in[3];     // [16384] i32
    float*       out = (float*)d_out;          // [2048, 16384] f32

    coef_kernel<<<OUT_DIM / 128, 128>>>(w, ia, ib);

    cudaFuncSetAttribute(logic_kernel,
                         cudaFuncAttributeMaxDynamicSharedMemorySize, SMEM_BYTES);

    logic_kernel<<<B_ROWS / ROWS_PER_CTA, THREADS, SMEM_BYTES>>>(x, out);  // 512 CTAs
}

// round 15
// speedup vs baseline: 1.4140x; 1.4140x over previous
#include <cuda_runtime.h>
#include <cuda_fp16.h>

#define IN_DIM   8192
#define OUT_DIM  16384
#define B_ROWS   2048

constexpr int THREADS         = 1024;
constexpr int SLAB_ROWS       = 8;                        // fp16 rows per smem slot
constexpr int PHASES          = 2;                        // row-slabs per CTA
constexpr int ROWS_PER_CTA    = SLAB_ROWS * PHASES;       // 16
constexpr int COLS_PER_THREAD = OUT_DIM / THREADS;        // 16
constexpr int SLAB_BYTES      = IN_DIM * SLAB_ROWS * 2;   // 128 KB
constexpr int IDX_BYTES       = OUT_DIM * 4;              // 64 KB
constexpr int SMEM_BYTES      = SLAB_BYTES + IDX_BYTES;   // 192 KB

// 16-byte slot holding 8 fp16 batch rows of one input column.
struct alignas(16) H8 { half2 h[4]; };
// 8-byte fp16 coefficient quad: {c1, ca}, {cb, cab}.
struct alignas(8) CF4 { __half2 p01; __half2 p23; };

// Precomputed per-output-column data.
__device__ CF4      g_cf [OUT_DIM];   // out = c1 + ca*a + cb*b + cab*ab
__device__ unsigned g_idx[OUT_DIM];   // idx_a | (idx_b << 16)

// ---------------------------------------------------------------------------
// Kernel 1: softmax(weights) -> affine coefficients (fp16); pack idx pairs.
// Triggers PDL immediately so logic_kernel can start staging concurrently.
// ---------------------------------------------------------------------------
__global__ void coef_kernel(const float* __restrict__ w,
                            const int*   __restrict__ idx_a,
                            const int*   __restrict__ idx_b)
{
    cudaTriggerProgrammaticLaunchCompletion();

    int o = blockIdx.x * blockDim.x + threadIdx.x;
    if (o >= OUT_DIM) return;

    const float4* w4 = reinterpret_cast<const float4*>(w + (size_t)o * 16);
    float v[16];
#pragma unroll
    for (int q = 0; q < 4; q++) {
        float4 t = w4[q];
        v[4 * q + 0] = t.x; v[4 * q + 1] = t.y;
        v[4 * q + 2] = t.z; v[4 * q + 3] = t.w;
    }

    float m = -1e30f;
#pragma unroll
    for (int i = 0; i < 16; i++) m = fmaxf(m, v[i]);
    float s = 0.0f;
#pragma unroll
    for (int i = 0; i < 16; i++) {
        v[i] = __expf(v[i] - m);
        s += v[i];
    }
    float inv = 1.0f / s;
#pragma unroll
    for (int i = 0; i < 16; i++) v[i] *= inv;

    // Gate table (difflogic order); gate 0 == 0 so v[0] unused.
    float c1  = v[8] + v[9] + v[10] + v[11] + v[12] + v[13] + v[14] + v[15];
    float ca  = v[2] + v[3] + v[6] + v[7] - v[8] - v[9] - v[12] - v[13];
    float cb  = v[4] + v[5] + v[6] + v[7] - v[8] - v[9] - v[10] - v[11];
    float cab = v[1] - v[2] - v[4] - 2.0f * v[6] - v[7]
              + v[8] + 2.0f * v[9] + v[11] + v[13] - v[14];

    CF4 cf;
    cf.p01 = __floats2half2_rn(c1, ca);
    cf.p23 = __floats2half2_rn(cb, cab);
    g_cf[o]  = cf;
    g_idx[o] = (unsigned)idx_a[o] | ((unsigned)idx_b[o] << 16);
}

// ---------------------------------------------------------------------------
// Kernel 2: one CTA = 16 batch rows x all 16384 cols, as two 8-row phases.
// Phase-0 x staging overlaps coef_kernel via PDL; staging loads use __ldcs
// (x is read exactly once chip-wide -> keep L2 for stores + metadata).
// ---------------------------------------------------------------------------
__global__ __launch_bounds__(THREADS, 1)
void logic_kernel(const float* __restrict__ x,
                  float*       __restrict__ out)
{
    extern __shared__ char smem[];
    H8*       sx   = reinterpret_cast<H8*>(smem);                     // [IN_DIM]
    unsigned* sidx = reinterpret_cast<unsigned*>(smem + SLAB_BYTES);  // [OUT_DIM]

    const int lane = threadIdx.x & 31;
    const int warp = threadIdx.x >> 5;
    constexpr int NWARPS = THREADS / 32;

#pragma unroll
    for (int ph = 0; ph < PHASES; ph++) {
        const int row0 = blockIdx.x * ROWS_PER_CTA + ph * SLAB_ROWS;

        if (ph > 0) __syncthreads();  // previous phase's smem reads done

        // Transposed fp16 staging: per 32-column group, 8 coalesced row loads
        // (streaming, evict-first), convert to half, one contiguous STS.128
        // per lane (conflict-free). Phase 0 overlaps coef_kernel via PDL.
        const float* xb = x + (size_t)row0 * IN_DIM;
#pragma unroll
        for (int g = warp; g < IN_DIM / 32; g += NWARPS) {
            int col = g * 32 + lane;
            H8 v;
#pragma unroll
            for (int p = 0; p < 4; p++) {
                v.h[p] = make_half2(
                    __float2half_rn(__ldcs(xb + (size_t)(2 * p + 0) * IN_DIM + col)),
                    __float2half_rn(__ldcs(xb + (size_t)(2 * p + 1) * IN_DIM + col)));
            }
            sx[col] = v;
        }

        if (ph == 0) {
            // Wait for coef_kernel's writes, then pull idx into smem.
            cudaGridDependencySynchronize();
            const uint4* gi = reinterpret_cast<const uint4*>(g_idx);
            uint4*       si = reinterpret_cast<uint4*>(sidx);
#pragma unroll
            for (int i = threadIdx.x; i < OUT_DIM / 4; i += THREADS)
                si[i] = gi[i];
        }
        __syncthreads();

#pragma unroll
        for (int c = 0; c < COLS_PER_THREAD; c++) {
            const int col = c * THREADS + threadIdx.x;
            const unsigned id = sidx[col];
            const CF4      cw = g_cf[col];

            const float2 c01 = __half22float2(cw.p01);  // {c1, ca}
            const float2 c23 = __half22float2(cw.p23);  // {cb, cab}

            const H8 a8 = sx[id & 0xFFFFu];   // 8 batch rows in one LDS.128
            const H8 b8 = sx[id >> 16];

            float* o0 = out + (size_t)row0 * OUT_DIM + col;
#pragma unroll
            for (int p = 0; p < 4; p++) {
                float2 af = __half22float2(a8.h[p]);
                float2 bf = __half22float2(b8.h[p]);
                __stcs(o0 + (size_t)(2 * p + 0) * OUT_DIM,
                       fmaf(c23.y, af.x * bf.x, fmaf(c23.x, bf.x, fmaf(c01.y, af.x, c01.x))));
                __stcs(o0 + (size_t)(2 * p + 1) * OUT_DIM,
                       fmaf(c23.y, af.y * bf.y, fmaf(c23.x, bf.y, fmaf(c01.y, af.y, c01.x))));
            }
        }
    }
}

// ---------------------------------------------------------------------------
// Launch: coef_kernel, then logic_kernel with PDL so its staging overlaps.
// ---------------------------------------------------------------------------
extern "C" void kernel_launch(void* const* d_in, const int* in_sizes, int n_in,
                              void* d_out, int out_size)
{
    const float* x  = (const float*)d_in[0];   // [2048, 8192] f32
    const float* w  = (const float*)d_in[1];   // [16384, 16]  f32
    const int*   ia = (const int*)d_in[2];     // [16384] i32
    const int*   ib = (const int*)d_in[3];     // [16384] i32
    float*       out = (float*)d_out;          // [2048, 16384] f32

    coef_kernel<<<OUT_DIM / 128, 128>>>(w, ia, ib);

    cudaFuncSetAttribute(logic_kernel,
                         cudaFuncAttributeMaxDynamicSharedMemorySize, SMEM_BYTES);

    cudaLaunchConfig_t cfg = {};
    cfg.gridDim          = dim3(B_ROWS / ROWS_PER_CTA);   // 128 CTAs
    cfg.blockDim         = dim3(THREADS);
    cfg.dynamicSmemBytes = SMEM_BYTES;
    cudaLaunchAttribute attrs[1];
    attrs[0].id = cudaLaunchAttributeProgrammaticStreamSerialization;
    attrs[0].val.programmaticStreamSerializationAllowed = 1;
    cfg.attrs    = attrs;
    cfg.numAttrs = 1;

    cudaLaunchKernelEx(&cfg, logic_kernel, x, out);
}

// round 16
// speedup vs baseline: 1.4747x; 1.0429x over previous
#include <cuda_runtime.h>
#include <cuda_fp16.h>

#define IN_DIM   8192
#define OUT_DIM  16384
#define B_ROWS   2048

constexpr int THREADS         = 1024;
constexpr int SLAB_ROWS       = 8;                        // fp16 rows per smem slot
constexpr int PHASES          = 2;                        // row-slabs per CTA
constexpr int ROWS_PER_CTA    = SLAB_ROWS * PHASES;       // 16
constexpr int COLS_PER_THREAD = OUT_DIM / THREADS;        // 16
constexpr int SLAB_BYTES      = IN_DIM * SLAB_ROWS * 2;   // 128 KB
constexpr int IDX_BYTES       = OUT_DIM * 4;              // 64 KB
constexpr int SMEM_BYTES      = SLAB_BYTES + IDX_BYTES;   // 192 KB

// 16-byte slot holding 8 fp16 batch rows of one input column.
struct alignas(16) H8 { half2 h[4]; };
// 8-byte fp16 coefficient quad: {c1, ca}, {cb, cab}.
struct alignas(8) CF4 { __half2 p01; __half2 p23; };

// Precomputed per-output-column data.
__device__ CF4      g_cf [OUT_DIM];   // out = c1 + ca*a + cb*b + cab*ab
__device__ unsigned g_idx[OUT_DIM];   // idx_a | (idx_b << 16)

// ---------------------------------------------------------------------------
// Kernel 1: softmax(weights) -> affine coefficients (fp16); pack idx pairs.
// Triggers PDL immediately so logic_kernel can start staging concurrently.
// ---------------------------------------------------------------------------
__global__ void coef_kernel(const float* __restrict__ w,
                            const int*   __restrict__ idx_a,
                            const int*   __restrict__ idx_b)
{
    cudaTriggerProgrammaticLaunchCompletion();

    int o = blockIdx.x * blockDim.x + threadIdx.x;
    if (o >= OUT_DIM) return;

    const float4* w4 = reinterpret_cast<const float4*>(w + (size_t)o * 16);
    float v[16];
#pragma unroll
    for (int q = 0; q < 4; q++) {
        float4 t = w4[q];
        v[4 * q + 0] = t.x; v[4 * q + 1] = t.y;
        v[4 * q + 2] = t.z; v[4 * q + 3] = t.w;
    }

    float m = -1e30f;
#pragma unroll
    for (int i = 0; i < 16; i++) m = fmaxf(m, v[i]);
    float s = 0.0f;
#pragma unroll
    for (int i = 0; i < 16; i++) {
        v[i] = __expf(v[i] - m);
        s += v[i];
    }
    float inv = 1.0f / s;
#pragma unroll
    for (int i = 0; i < 16; i++) v[i] *= inv;

    // Gate table (difflogic order); gate 0 == 0 so v[0] unused.
    float c1  = v[8] + v[9] + v[10] + v[11] + v[12] + v[13] + v[14] + v[15];
    float ca  = v[2] + v[3] + v[6] + v[7] - v[8] - v[9] - v[12] - v[13];
    float cb  = v[4] + v[5] + v[6] + v[7] - v[8] - v[9] - v[10] - v[11];
    float cab = v[1] - v[2] - v[4] - 2.0f * v[6] - v[7]
              + v[8] + 2.0f * v[9] + v[11] + v[13] - v[14];

    CF4 cf;
    cf.p01 = __floats2half2_rn(c1, ca);
    cf.p23 = __floats2half2_rn(cb, cab);
    g_cf[o]  = cf;
    g_idx[o] = (unsigned)idx_a[o] | ((unsigned)idx_b[o] << 16);
}

// ---------------------------------------------------------------------------
// Kernel 2: one CTA = 16 batch rows x all 16384 cols, as two 8-row phases.
// Phase-0 x staging overlaps coef_kernel via PDL; during phase-0 compute we
// prefetch phase-1's x slab into L2 so phase-1 staging hits L2, not DRAM.
// ---------------------------------------------------------------------------
__global__ __launch_bounds__(THREADS, 1)
void logic_kernel(const float* __restrict__ x,
                  float*       __restrict__ out)
{
    extern __shared__ char smem[];
    H8*       sx   = reinterpret_cast<H8*>(smem);                     // [IN_DIM]
    unsigned* sidx = reinterpret_cast<unsigned*>(smem + SLAB_BYTES);  // [OUT_DIM]

    const int lane = threadIdx.x & 31;
    const int warp = threadIdx.x >> 5;
    constexpr int NWARPS = THREADS / 32;

#pragma unroll
    for (int ph = 0; ph < PHASES; ph++) {
        const int row0 = blockIdx.x * ROWS_PER_CTA + ph * SLAB_ROWS;

        if (ph > 0) __syncthreads();  // previous phase's smem reads done

        // Transposed fp16 staging: per 32-column group, 8 coalesced row loads
        // (streaming, evict-first), convert to half, one contiguous STS.128
        // per lane (conflict-free). Phase 0 overlaps coef_kernel via PDL.
        const float* xb = x + (size_t)row0 * IN_DIM;
#pragma unroll
        for (int g = warp; g < IN_DIM / 32; g += NWARPS) {
            int col = g * 32 + lane;
            H8 v;
#pragma unroll
            for (int p = 0; p < 4; p++) {
                v.h[p] = make_half2(
                    __float2half_rn(__ldcs(xb + (size_t)(2 * p + 0) * IN_DIM + col)),
                    __float2half_rn(__ldcs(xb + (size_t)(2 * p + 1) * IN_DIM + col)));
            }
            sx[col] = v;
        }

        if (ph == 0) {
            // Wait for coef_kernel's writes, then pull idx into smem.
            cudaGridDependencySynchronize();
            const uint4* gi = reinterpret_cast<const uint4*>(g_idx);
            uint4*       si = reinterpret_cast<uint4*>(sidx);
#pragma unroll
            for (int i = threadIdx.x; i < OUT_DIM / 4; i += THREADS)
                si[i] = gi[i];
        }
        __syncthreads();

        if (ph == 0) {
            // Prefetch phase-1's x slab (256 KB/CTA = 2 lines/thread) into L2
            // under the phase-0 compute shadow.
            const float* xn = x + ((size_t)blockIdx.x * ROWS_PER_CTA + SLAB_ROWS) * IN_DIM;
            const char* p0 = reinterpret_cast<const char*>(xn) + (size_t)threadIdx.x * 128;
#pragma unroll
            for (int q = 0; q < 2; q++) {
                asm volatile("prefetch.global.L2 [%0];" ::
                             "l"(p0 + (size_t)q * THREADS * 128));
            }
        }

#pragma unroll
        for (int c = 0; c < COLS_PER_THREAD; c++) {
            const int col = c * THREADS + threadIdx.x;
            const unsigned id = sidx[col];
            const CF4      cw = g_cf[col];

            const float2 c01 = __half22float2(cw.p01);  // {c1, ca}
            const float2 c23 = __half22float2(cw.p23);  // {cb, cab}

            const H8 a8 = sx[id & 0xFFFFu];   // 8 batch rows in one LDS.128
            const H8 b8 = sx[id >> 16];

            float* o0 = out + (size_t)row0 * OUT_DIM + col;
#pragma unroll
            for (int p = 0; p < 4; p++) {
                float2 af = __half22float2(a8.h[p]);
                float2 bf = __half22float2(b8.h[p]);
                __stcs(o0 + (size_t)(2 * p + 0) * OUT_DIM,
                       fmaf(c23.y, af.x * bf.x, fmaf(c23.x, bf.x, fmaf(c01.y, af.x, c01.x))));
                __stcs(o0 + (size_t)(2 * p + 1) * OUT_DIM,
                       fmaf(c23.y, af.y * bf.y, fmaf(c23.x, bf.y, fmaf(c01.y, af.y, c01.x))));
            }
        }
    }
}

// ---------------------------------------------------------------------------
// Launch: coef_kernel, then logic_kernel with PDL so its staging overlaps.
// ---------------------------------------------------------------------------
extern "C" void kernel_launch(void* const* d_in, const int* in_sizes, int n_in,
                              void* d_out, int out_size)
{
    const float* x  = (const float*)d_in[0];   // [2048, 8192] f32
    const float* w  = (const float*)d_in[1];   // [16384, 16]  f32
    const int*   ia = (const int*)d_in[2];     // [16384] i32
    const int*   ib = (const int*)d_in[3];     // [16384] i32
    float*       out = (float*)d_out;          // [2048, 16384] f32

    coef_kernel<<<OUT_DIM / 128, 128>>>(w, ia, ib);

    cudaFuncSetAttribute(logic_kernel,
                         cudaFuncAttributeMaxDynamicSharedMemorySize, SMEM_BYTES);

    cudaLaunchConfig_t cfg = {};
    cfg.gridDim          = dim3(B_ROWS / ROWS_PER_CTA);   // 128 CTAs
    cfg.blockDim         = dim3(THREADS);
    cfg.dynamicSmemBytes = SMEM_BYTES;
    cudaLaunchAttribute attrs[1];
    attrs[0].id = cudaLaunchAttributeProgrammaticStreamSerialization;
    attrs[0].val.programmaticStreamSerializationAllowed = 1;
    cfg.attrs    = attrs;
    cfg.numAttrs = 1;

    cudaLaunchKernelEx(&cfg, logic_kernel, x, out);
}